// round 13
// baseline (speedup 1.0000x reference)
#include <cuda_runtime.h>
#include <cuda_bf16.h>
#include <cstdint>

// ---------------------------------------------------------------------------
// Problem constants
// ---------------------------------------------------------------------------
#define BATCH 4
#define SEQ   2048
#define EMBD  1024
#define NHEAD 16
#define HDIM  64
#define BT    (BATCH*SEQ)        // 8192
#define C3    (3*EMBD)           // 3072

// ---------------------------------------------------------------------------
// Scratch (device globals — no allocation allowed)
// ---------------------------------------------------------------------------
__device__ __nv_bfloat16 g_qkvh[(size_t)BT * C3];
__device__ __nv_bfloat16 g_qkvl[(size_t)BT * C3];
__device__ __nv_bfloat16 g_xh[(size_t)BT * EMBD];
__device__ __nv_bfloat16 g_xl[(size_t)BT * EMBD];
__device__ __nv_bfloat16 g_wah[(size_t)EMBD * C3];
__device__ __nv_bfloat16 g_wal[(size_t)EMBD * C3];
__device__ __nv_bfloat16 g_wph[(size_t)EMBD * EMBD];
__device__ __nv_bfloat16 g_wpl[(size_t)EMBD * EMBD];
__device__ __nv_bfloat16 g_yh[(size_t)BT * EMBD];
__device__ __nv_bfloat16 g_yl[(size_t)BT * EMBD];

// ---------------------------------------------------------------------------
// PTX helpers (sm_80+ portable: mma.sync / ldmatrix / cp.async)
// ---------------------------------------------------------------------------
__device__ __forceinline__ uint32_t smem_to_u32(const void* smem_ptr) {
    uint32_t addr;
    asm("{ .reg .u64 tmp; cvta.to.shared.u64 tmp, %1; cvt.u32.u64 %0, tmp; }"
        : "=r"(addr) : "l"(smem_ptr));
    return addr;
}

#define CP_ASYNC16(saddr, gptr) \
    asm volatile("cp.async.cg.shared.global [%0], [%1], 16;" \
        :: "r"(saddr), "l"(gptr) : "memory")
#define CP_ASYNC_COMMIT() asm volatile("cp.async.commit_group;" ::: "memory")
#define CP_ASYNC_WAIT0()  asm volatile("cp.async.wait_group 0;" ::: "memory")
#define CP_ASYNC_WAIT1()  asm volatile("cp.async.wait_group 1;" ::: "memory")

#define LDMATRIX_X4(r0,r1,r2,r3, addr) \
    asm volatile("ldmatrix.sync.aligned.m8n8.x4.shared.b16 {%0,%1,%2,%3}, [%4];" \
        : "=r"(r0), "=r"(r1), "=r"(r2), "=r"(r3) : "r"(addr))

#define LDMATRIX_X4_T(r0,r1,r2,r3, addr) \
    asm volatile("ldmatrix.sync.aligned.m8n8.x4.trans.shared.b16 {%0,%1,%2,%3}, [%4];" \
        : "=r"(r0), "=r"(r1), "=r"(r2), "=r"(r3) : "r"(addr))

#define MMA_16816(d, a, b0v, b1v) \
    asm volatile( \
        "mma.sync.aligned.m16n8k16.row.col.f32.bf16.bf16.f32 " \
        "{%0,%1,%2,%3}, {%4,%5,%6,%7}, {%8,%9}, {%0,%1,%2,%3};" \
        : "+f"((d)[0]), "+f"((d)[1]), "+f"((d)[2]), "+f"((d)[3]) \
        : "r"((a)[0]), "r"((a)[1]), "r"((a)[2]), "r"((a)[3]), \
          "r"(b0v), "r"(b1v))

// split two fp32 into packed bf16x2 hi and lo
__device__ __forceinline__ void split2(float a, float b, uint32_t& h, uint32_t& l) {
    __nv_bfloat162 hh = __floats2bfloat162_rn(a, b);
    float2 hf = __bfloat1622float2(hh);
    __nv_bfloat162 ll = __floats2bfloat162_rn(a - hf.x, b - hf.y);
    h = *(uint32_t*)&hh;
    l = *(uint32_t*)&ll;
}

// ---------------------------------------------------------------------------
// Fused split: x, W_attn, W_proj -> bf16 hi/lo in ONE launch.
// Segments (in float4 units): x: NX4, W_attn: NWA4, W_proj: NWP4.
// ---------------------------------------------------------------------------
#define NX4  (BT * EMBD / 4)
#define NWA4 (EMBD * C3 / 4)
#define NWP4 (EMBD * EMBD / 4)
#define NSPLIT4 (NX4 + NWA4 + NWP4)

__global__ __launch_bounds__(256) void split_all_bf16(
    const float* __restrict__ x, const float* __restrict__ wa,
    const float* __restrict__ wp,
    __nv_bfloat16* __restrict__ xh, __nv_bfloat16* __restrict__ xl,
    __nv_bfloat16* __restrict__ wah, __nv_bfloat16* __restrict__ wal,
    __nv_bfloat16* __restrict__ wph, __nv_bfloat16* __restrict__ wpl)
{
    int i = blockIdx.x * 256 + threadIdx.x;
    if (i >= NSPLIT4) return;
    const float* src;
    __nv_bfloat16 *hi, *lo;
    int j = i;
    if (j < NX4)                { src = x;  hi = xh;  lo = xl; }
    else if ((j -= NX4) < NWA4) { src = wa; hi = wah; lo = wal; }
    else { j -= NWA4;             src = wp; hi = wph; lo = wpl; }

    float4 v = ((const float4*)src)[j];
    uint32_t h0, l0, h1, l1;
    split2(v.x, v.y, h0, l0);
    split2(v.z, v.w, h1, l1);
    ((uint32_t*)hi)[2*j]     = h0;
    ((uint32_t*)hi)[2*j + 1] = h1;
    ((uint32_t*)lo)[2*j]     = l0;
    ((uint32_t*)lo)[2*j + 1] = l1;
}

// ---------------------------------------------------------------------------
// mma.sync bf16x3 GEMM — unchanged from R12 passing (at measured HMMA ceiling).
// ---------------------------------------------------------------------------
#define GOFF_AH 0u
#define GOFF_AL 10240u
#define GOFF_BH 20480u
#define GOFF_BL 29184u
#define GBUF    37888u
#define GEMM_SMEM_BYTES (2u * GBUF)

template<int SPLIT_OUT>
__global__ __launch_bounds__(256) void gemm_mma_bf16x3(
    const __nv_bfloat16* __restrict__ Ah, const __nv_bfloat16* __restrict__ Al,
    const __nv_bfloat16* __restrict__ Bh, const __nv_bfloat16* __restrict__ Bl,
    const float* __restrict__ bias, float* __restrict__ Cout,
    __nv_bfloat16* __restrict__ Ch, __nv_bfloat16* __restrict__ Cl,
    int M, int N, int K)
{
    extern __shared__ __align__(16) char smem[];
    const uint32_t sb = smem_to_u32(smem);
    const int tid  = threadIdx.x;
    const int warp = tid >> 5;
    const int lane = tid & 31;
    const int wm = warp & 1;
    const int wn = warp >> 1;
    const int row0 = blockIdx.y * 128;
    const int col0 = blockIdx.x * 128;

    const int ar = tid >> 2;
    const int ac = (tid & 3) * 8;
    const int bkr = tid >> 4;
    const int bnc = (tid & 15) * 8;

    const int nchunk = K >> 5;

    float acc[4][4][4];
    #pragma unroll
    for (int mt = 0; mt < 4; mt++)
        #pragma unroll
        for (int nt = 0; nt < 4; nt++)
            #pragma unroll
            for (int r = 0; r < 4; r++) acc[mt][nt][r] = 0.0f;

    {
        #pragma unroll
        for (int p = 0; p < 2; p++) {
            int r = ar + p * 64;
            CP_ASYNC16(sb + GOFF_AH + r*80 + ac*2, Ah + (size_t)(row0 + r) * K + ac);
            CP_ASYNC16(sb + GOFF_AL + r*80 + ac*2, Al + (size_t)(row0 + r) * K + ac);
            int kr = bkr + p * 16;
            CP_ASYNC16(sb + GOFF_BH + kr*272 + bnc*2, Bh + (size_t)kr * N + col0 + bnc);
            CP_ASYNC16(sb + GOFF_BL + kr*272 + bnc*2, Bl + (size_t)kr * N + col0 + bnc);
        }
        CP_ASYNC_COMMIT();
    }

    uint32_t buf = 0;
    for (int c = 0; c < nchunk; c++) {
        CP_ASYNC_WAIT0();
        __syncthreads();

        if (c + 1 < nchunk) {
            const uint32_t nb = sb + (buf ^ 1) * GBUF;
            const int kc0 = (c + 1) << 5;
            #pragma unroll
            for (int p = 0; p < 2; p++) {
                int r = ar + p * 64;
                CP_ASYNC16(nb + GOFF_AH + r*80 + ac*2, Ah + (size_t)(row0 + r) * K + kc0 + ac);
                CP_ASYNC16(nb + GOFF_AL + r*80 + ac*2, Al + (size_t)(row0 + r) * K + kc0 + ac);
                int kr = bkr + p * 16;
                CP_ASYNC16(nb + GOFF_BH + kr*272 + bnc*2, Bh + (size_t)(kc0 + kr) * N + col0 + bnc);
                CP_ASYNC16(nb + GOFF_BL + kr*272 + bnc*2, Bl + (size_t)(kc0 + kr) * N + col0 + bnc);
            }
            CP_ASYNC_COMMIT();
        }

        const uint32_t cb = sb + buf * GBUF;
        uint32_t a_h[2][4][4], a_l[2][4][4];
        uint32_t b_h[2][2][4], b_l[2][2][4];
        const int g = lane >> 3;
        #pragma unroll
        for (int s = 0; s < 2; s++) {
            const int arow_base = wm * 64 + (lane & 15);
            const int acol = (s * 16 + (lane >> 4) * 8) * 2;
            #pragma unroll
            for (int mt = 0; mt < 4; mt++) {
                uint32_t off = (uint32_t)((arow_base + mt * 16) * 80 + acol);
                LDMATRIX_X4(a_h[s][mt][0], a_h[s][mt][1], a_h[s][mt][2], a_h[s][mt][3],
                            cb + GOFF_AH + off);
                LDMATRIX_X4(a_l[s][mt][0], a_l[s][mt][1], a_l[s][mt][2], a_l[s][mt][3],
                            cb + GOFF_AL + off);
            }
            const int krow = s * 16 + (g & 1) * 8 + (lane & 7);
            #pragma unroll
            for (int ntp = 0; ntp < 2; ntp++) {
                const int ncol = wn * 32 + ntp * 16 + (g >> 1) * 8;
                uint32_t off = (uint32_t)(krow * 272 + ncol * 2);
                LDMATRIX_X4_T(b_h[s][ntp][0], b_h[s][ntp][1], b_h[s][ntp][2], b_h[s][ntp][3],
                              cb + GOFF_BH + off);
                LDMATRIX_X4_T(b_l[s][ntp][0], b_l[s][ntp][1], b_l[s][ntp][2], b_l[s][ntp][3],
                              cb + GOFF_BL + off);
            }
        }
        #pragma unroll
        for (int s = 0; s < 2; s++) {
            #pragma unroll
            for (int combo = 0; combo < 3; combo++) {
                #pragma unroll
                for (int mt = 0; mt < 4; mt++) {
                    const uint32_t* av = (combo == 2) ? a_l[s][mt] : a_h[s][mt];
                    #pragma unroll
                    for (int nt = 0; nt < 4; nt++) {
                        const uint32_t b0v = (combo == 1) ? b_l[s][nt >> 1][(nt & 1) * 2]
                                                          : b_h[s][nt >> 1][(nt & 1) * 2];
                        const uint32_t b1v = (combo == 1) ? b_l[s][nt >> 1][(nt & 1) * 2 + 1]
                                                          : b_h[s][nt >> 1][(nt & 1) * 2 + 1];
                        MMA_16816(acc[mt][nt], av, b0v, b1v);
                    }
                }
            }
        }
        buf ^= 1;
    }

    const int er = (lane >> 2);
    const int ec = (lane & 3) * 2;
    #pragma unroll
    for (int mt = 0; mt < 4; mt++) {
        #pragma unroll
        for (int nt = 0; nt < 4; nt++) {
            const int r  = row0 + wm * 64 + mt * 16 + er;
            const int cc = col0 + wn * 32 + nt * 8 + ec;
            float2 bv = *(const float2*)(bias + cc);
            float o0x = acc[mt][nt][0] + bv.x;
            float o0y = acc[mt][nt][1] + bv.y;
            float o1x = acc[mt][nt][2] + bv.x;
            float o1y = acc[mt][nt][3] + bv.y;
            if (SPLIT_OUT) {
                uint32_t h0, l0, h1, l1;
                split2(o0x, o0y, h0, l0);
                split2(o1x, o1y, h1, l1);
                *(uint32_t*)(Ch + (size_t)r * N + cc)       = h0;
                *(uint32_t*)(Cl + (size_t)r * N + cc)       = l0;
                *(uint32_t*)(Ch + (size_t)(r + 8) * N + cc) = h1;
                *(uint32_t*)(Cl + (size_t)(r + 8) * N + cc) = l1;
            } else {
                *(float2*)(Cout + (size_t)r * N + cc)       = make_float2(o0x, o0y);
                *(float2*)(Cout + (size_t)(r + 8) * N + cc) = make_float2(o1x, o1y);
            }
        }
    }
}

// ---------------------------------------------------------------------------
// Flash attention (causal), mma.sync bf16x3.
// NEW: 3-buffer KV ring; the post-PV __syncthreads is removed. Safety: the
// top-of-tile barrier at kt guarantees all warps finished reading tile kt-1,
// so the end-of-tile prefetch into buffer (kt+2)%3 == (kt-1)%3 cannot race.
// One barrier per tile instead of two; prefetch issues earlier.
// ---------------------------------------------------------------------------
#define BKV 64
#define AROW 144              // bytes per smem row
#define OKH 0u
#define OKL 9216u
#define OVH 18432u
#define OVL 27648u
#define ABUF 36864u
#define ATTN_SMEM_BYTES (3u * ABUF)

__global__ __launch_bounds__(256) void attn_mma(
    const __nv_bfloat16* __restrict__ qkvh, const __nv_bfloat16* __restrict__ qkvl,
    __nv_bfloat16* __restrict__ Yh, __nv_bfloat16* __restrict__ Yl)
{
    extern __shared__ __align__(16) char smem[];
    const uint32_t sb = smem_to_u32(smem);
    const int tid  = threadIdx.x;
    const int warp = tid >> 5;
    const int lane = tid & 31;

    const int qt = (int)(gridDim.x - 1 - blockIdx.x);   // heavy tiles first
    const int bh = blockIdx.y;
    const int b  = bh >> 4;
    const int h  = bh & 15;

    const size_t rowbase = (size_t)b * SEQ * C3 + h * HDIM;
    const __nv_bfloat16* qh_g = qkvh + rowbase;
    const __nv_bfloat16* ql_g = qkvl + rowbase;
    const __nv_bfloat16* kh_g = qkvh + rowbase + EMBD;
    const __nv_bfloat16* kl_g = qkvl + rowbase + EMBD;
    const __nv_bfloat16* vh_g = qkvh + rowbase + 2 * EMBD;
    const __nv_bfloat16* vl_g = qkvl + rowbase + 2 * EMBD;

    // ---- stage Q (128 rows x 64) hi/lo into smem (buffer 0), then to regs ----
    {
        #pragma unroll
        for (int it = 0; it < 4; it++) {
            int i = tid + it * 256;
            int row = i >> 3, ch = i & 7;
            const size_t go = (size_t)(qt * 128 + row) * C3 + ch * 8;
            CP_ASYNC16(sb + row * AROW + ch * 16,         qh_g + go);
            CP_ASYNC16(sb + 18432 + row * AROW + ch * 16, ql_g + go);
        }
        CP_ASYNC_COMMIT();
        CP_ASYNC_WAIT0();
        __syncthreads();
    }

    uint32_t aqh[4][4], aql[4][4];
    {
        const int arow = warp * 16 + (lane & 15);
        const int acby = (lane >> 4) * 16;
        #pragma unroll
        for (int kt4 = 0; kt4 < 4; kt4++) {
            uint32_t off = (uint32_t)(arow * AROW + kt4 * 32 + acby);
            LDMATRIX_X4(aqh[kt4][0], aqh[kt4][1], aqh[kt4][2], aqh[kt4][3], sb + off);
            LDMATRIX_X4(aql[kt4][0], aql[kt4][1], aql[kt4][2], aql[kt4][3], sb + 18432 + off);
        }
    }
    __syncthreads();   // done reading Q smem before K/V overwrite

    // ---- softmax state + O accumulators ----
    float m0 = -1e30f, m1 = -1e30f, l0 = 0.0f, l1 = 0.0f;
    float o[8][4];
    #pragma unroll
    for (int nt = 0; nt < 8; nt++)
        #pragma unroll
        for (int r = 0; r < 4; r++) o[nt][r] = 0.0f;

    const int nkv = 2 * qt + 2;

    // prefetch KV tiles 0 and 1 (into ring slots 0, 1)
    #pragma unroll
    for (int pf = 0; pf < 2; pf++) {
        if (pf < nkv) {
            const uint32_t dst = sb + pf * ABUF;
            #pragma unroll
            for (int it = 0; it < 2; it++) {
                int i = tid + it * 256;
                int row = i >> 3, ch = i & 7;
                const size_t go = (size_t)(pf * BKV + row) * C3 + ch * 8;
                const uint32_t so = row * AROW + ch * 16;
                CP_ASYNC16(dst + OKH + so, kh_g + go);
                CP_ASYNC16(dst + OKL + so, kl_g + go);
                CP_ASYNC16(dst + OVH + so, vh_g + go);
                CP_ASYNC16(dst + OVL + so, vl_g + go);
            }
            CP_ASYNC_COMMIT();
        }
    }

    const float scale = 0.125f;  // 1/sqrt(64)

    for (int kt = 0; kt < nkv; kt++) {
        if (kt + 1 < nkv) { CP_ASYNC_WAIT1(); } else { CP_ASYNC_WAIT0(); }
        __syncthreads();   // single barrier per tile: tile kt ready, all warps past kt-1

        const uint32_t cb = sb + (uint32_t)(kt % 3) * ABUF;

        // ---- S = Qh*Kh^T + Qh*Kl^T + Ql*Kh^T  (m16 x n64, k=64) ----
        float s[8][4];
        #pragma unroll
        for (int nt = 0; nt < 8; nt++)
            #pragma unroll
            for (int r = 0; r < 4; r++) s[nt][r] = 0.0f;

        const int g = lane >> 3;
        #pragma unroll
        for (int kt4 = 0; kt4 < 4; kt4++) {
            uint32_t bkh[4][4], bkl[4][4];
            #pragma unroll
            for (int nt16 = 0; nt16 < 4; nt16++) {
                const int nrow = nt16 * 16 + (g & 1) * 8 + (lane & 7);
                const uint32_t off = (uint32_t)(nrow * AROW + kt4 * 32 + (g >> 1) * 16);
                LDMATRIX_X4(bkh[nt16][0], bkh[nt16][1], bkh[nt16][2], bkh[nt16][3], cb + OKH + off);
                LDMATRIX_X4(bkl[nt16][0], bkl[nt16][1], bkl[nt16][2], bkl[nt16][3], cb + OKL + off);
            }
            #pragma unroll
            for (int combo = 0; combo < 3; combo++) {
                const uint32_t* aq = (combo == 2) ? aql[kt4] : aqh[kt4];
                #pragma unroll
                for (int nt16 = 0; nt16 < 4; nt16++) {
                    #pragma unroll
                    for (int hv = 0; hv < 2; hv++) {
                        const int nt8 = nt16 * 2 + hv;
                        const uint32_t b0v = (combo == 1) ? bkl[nt16][hv]     : bkh[nt16][hv];
                        const uint32_t b1v = (combo == 1) ? bkl[nt16][2 + hv] : bkh[nt16][2 + hv];
                        MMA_16816(s[nt8], aq, b0v, b1v);
                    }
                }
            }
        }

        // ---- online softmax ----
        const bool need_mask = (kt >= 2 * qt);
        const int r0g = qt * 128 + warp * 16 + (lane >> 2);
        const int r1g = r0g + 8;
        float rmax0 = -1e30f, rmax1 = -1e30f;
        #pragma unroll
        for (int nt = 0; nt < 8; nt++) {
            #pragma unroll
            for (int j = 0; j < 2; j++) {
                const int kc = kt * BKV + nt * 8 + (lane & 3) * 2 + j;
                float v0 = s[nt][j] * scale;
                float v1 = s[nt][2 + j] * scale;
                if (need_mask) {
                    if (kc > r0g) v0 = -1e30f;
                    if (kc > r1g) v1 = -1e30f;
                }
                s[nt][j] = v0;     rmax0 = fmaxf(rmax0, v0);
                s[nt][2 + j] = v1; rmax1 = fmaxf(rmax1, v1);
            }
        }
        rmax0 = fmaxf(rmax0, __shfl_xor_sync(0xffffffffu, rmax0, 1));
        rmax0 = fmaxf(rmax0, __shfl_xor_sync(0xffffffffu, rmax0, 2));
        rmax1 = fmaxf(rmax1, __shfl_xor_sync(0xffffffffu, rmax1, 1));
        rmax1 = fmaxf(rmax1, __shfl_xor_sync(0xffffffffu, rmax1, 2));

        const float mn0 = fmaxf(m0, rmax0);
        const float mn1 = fmaxf(m1, rmax1);
        const float alpha0 = __expf(m0 - mn0);
        const float alpha1 = __expf(m1 - mn1);
        m0 = mn0; m1 = mn1;

        float ps0 = 0.0f, ps1 = 0.0f;
        #pragma unroll
        for (int nt = 0; nt < 8; nt++) {
            #pragma unroll
            for (int j = 0; j < 2; j++) {
                float p0 = __expf(s[nt][j] - mn0);
                float p1 = __expf(s[nt][2 + j] - mn1);
                s[nt][j] = p0;     ps0 += p0;
                s[nt][2 + j] = p1; ps1 += p1;
            }
        }
        ps0 += __shfl_xor_sync(0xffffffffu, ps0, 1);
        ps0 += __shfl_xor_sync(0xffffffffu, ps0, 2);
        ps1 += __shfl_xor_sync(0xffffffffu, ps1, 1);
        ps1 += __shfl_xor_sync(0xffffffffu, ps1, 2);
        l0 = l0 * alpha0 + ps0;
        l1 = l1 * alpha1 + ps1;

        #pragma unroll
        for (int nt = 0; nt < 8; nt++) {
            o[nt][0] *= alpha0; o[nt][1] *= alpha0;
            o[nt][2] *= alpha1; o[nt][3] *= alpha1;
        }

        // ---- pack P -> bf16 hi/lo A-fragments ----
        uint32_t aph[4][4], apl[4][4];
        #pragma unroll
        for (int pt = 0; pt < 4; pt++) {
            split2(s[2*pt][0],   s[2*pt][1],   aph[pt][0], apl[pt][0]);
            split2(s[2*pt][2],   s[2*pt][3],   aph[pt][1], apl[pt][1]);
            split2(s[2*pt+1][0], s[2*pt+1][1], aph[pt][2], apl[pt][2]);
            split2(s[2*pt+1][2], s[2*pt+1][3], aph[pt][3], apl[pt][3]);
        }

        // ---- O += P @ V ----
        #pragma unroll
        for (int pt = 0; pt < 4; pt++) {
            uint32_t bvh[4][4], bvl[4][4];
            #pragma unroll
            for (int nt16 = 0; nt16 < 4; nt16++) {
                const int krow = pt * 16 + (g & 1) * 8 + (lane & 7);
                const uint32_t off = (uint32_t)(krow * AROW + nt16 * 32 + (g >> 1) * 16);
                LDMATRIX_X4_T(bvh[nt16][0], bvh[nt16][1], bvh[nt16][2], bvh[nt16][3], cb + OVH + off);
                LDMATRIX_X4_T(bvl[nt16][0], bvl[nt16][1], bvl[nt16][2], bvl[nt16][3], cb + OVL + off);
            }
            #pragma unroll
            for (int combo = 0; combo < 3; combo++) {
                const uint32_t* ap = (combo == 2) ? apl[pt] : aph[pt];
                #pragma unroll
                for (int nt16 = 0; nt16 < 4; nt16++) {
                    #pragma unroll
                    for (int hv = 0; hv < 2; hv++) {
                        const int nt8 = nt16 * 2 + hv;
                        const uint32_t b0v = (combo == 1) ? bvl[nt16][hv * 2]     : bvh[nt16][hv * 2];
                        const uint32_t b1v = (combo == 1) ? bvl[nt16][hv * 2 + 1] : bvh[nt16][hv * 2 + 1];
                        MMA_16816(o[nt8], ap, b0v, b1v);
                    }
                }
            }
        }

        // NO barrier here: 3-buffer ring makes the end-of-tile prefetch safe.
        if (kt + 2 < nkv) {
            const uint32_t dst = sb + (uint32_t)((kt + 2) % 3) * ABUF;
            #pragma unroll
            for (int it = 0; it < 2; it++) {
                int i = tid + it * 256;
                int row = i >> 3, ch = i & 7;
                const size_t go = (size_t)((kt + 2) * BKV + row) * C3 + ch * 8;
                const uint32_t so = row * AROW + ch * 16;
                CP_ASYNC16(dst + OKH + so, kh_g + go);
                CP_ASYNC16(dst + OKL + so, kl_g + go);
                CP_ASYNC16(dst + OVH + so, vh_g + go);
                CP_ASYNC16(dst + OVL + so, vl_g + go);
            }
            CP_ASYNC_COMMIT();
        }
    }

    // ---- epilogue: normalize, split to bf16 hi/lo, store ----
    const float inv0 = 1.0f / l0;
    const float inv1 = 1.0f / l1;
    const int tr0 = qt * 128 + warp * 16 + (lane >> 2);
    const size_t ybase = (size_t)b * SEQ * EMBD + h * HDIM;
    #pragma unroll
    for (int nt = 0; nt < 8; nt++) {
        const int col = nt * 8 + (lane & 3) * 2;
        uint32_t h0, lo0, h1, lo1;
        split2(o[nt][0] * inv0, o[nt][1] * inv0, h0, lo0);
        split2(o[nt][2] * inv1, o[nt][3] * inv1, h1, lo1);
        *(uint32_t*)(Yh + ybase + (size_t)tr0 * EMBD + col)       = h0;
        *(uint32_t*)(Yl + ybase + (size_t)tr0 * EMBD + col)       = lo0;
        *(uint32_t*)(Yh + ybase + (size_t)(tr0 + 8) * EMBD + col) = h1;
        *(uint32_t*)(Yl + ybase + (size_t)(tr0 + 8) * EMBD + col) = lo1;
    }
}

// ---------------------------------------------------------------------------
extern "C" void kernel_launch(void* const* d_in, const int* in_sizes, int n_in,
                              void* d_out, int out_size)
{
    const float* x      = (const float*)d_in[0];
    const float* W_attn = (const float*)d_in[1];
    const float* b_attn = (const float*)d_in[2];
    const float* W_proj = (const float*)d_in[3];
    const float* b_proj = (const float*)d_in[4];
    float* out = (float*)d_out;

    __nv_bfloat16 *qkvh, *qkvl, *xh, *xl, *wah, *wal, *wph, *wpl, *yh, *yl;
    cudaGetSymbolAddress((void**)&qkvh, g_qkvh);
    cudaGetSymbolAddress((void**)&qkvl, g_qkvl);
    cudaGetSymbolAddress((void**)&xh,  g_xh);
    cudaGetSymbolAddress((void**)&xl,  g_xl);
    cudaGetSymbolAddress((void**)&wah, g_wah);
    cudaGetSymbolAddress((void**)&wal, g_wal);
    cudaGetSymbolAddress((void**)&wph, g_wph);
    cudaGetSymbolAddress((void**)&wpl, g_wpl);
    cudaGetSymbolAddress((void**)&yh,  g_yh);
    cudaGetSymbolAddress((void**)&yl,  g_yl);

    cudaFuncSetAttribute(gemm_mma_bf16x3<0>,
                         cudaFuncAttributeMaxDynamicSharedMemorySize, GEMM_SMEM_BYTES);
    cudaFuncSetAttribute(gemm_mma_bf16x3<1>,
                         cudaFuncAttributeMaxDynamicSharedMemorySize, GEMM_SMEM_BYTES);
    cudaFuncSetAttribute(attn_mma,
                         cudaFuncAttributeMaxDynamicSharedMemorySize, ATTN_SMEM_BYTES);

    // 0) fused split of all inputs (one launch)
    {
        split_all_bf16<<<(NSPLIT4 + 255) / 256, 256>>>(
            x, W_attn, W_proj, xh, xl, wah, wal, wph, wpl);
    }
    // 1) QKV GEMM -> bf16 hi/lo qkv (bias fused, split fused)
    {
        dim3 grid(C3 / 128, BT / 128);
        gemm_mma_bf16x3<1><<<grid, 256, GEMM_SMEM_BYTES>>>(
            xh, xl, wah, wal, b_attn, nullptr, qkvh, qkvl, BT, C3, EMBD);
    }
    // 2) causal flash attention (3-buffer ring) -> bf16 hi/lo y
    {
        dim3 grid(SEQ / 128, BATCH * NHEAD);
        attn_mma<<<grid, 256, ATTN_SMEM_BYTES>>>(qkvh, qkvl, yh, yl);
    }
    // 3) proj GEMM -> fp32 out
    {
        dim3 grid(EMBD / 128, BT / 128);
        gemm_mma_bf16x3<0><<<grid, 256, GEMM_SMEM_BYTES>>>(
            yh, yl, wph, wpl, b_proj, out, nullptr, nullptr, BT, EMBD, EMBD);
    }
}

// round 15
// speedup vs baseline: 1.1668x; 1.1668x over previous
#include <cuda_runtime.h>
#include <cuda_fp16.h>
#include <cstdint>

// ---------------------------------------------------------------------------
// Problem constants
// ---------------------------------------------------------------------------
#define BATCH 4
#define SEQ   2048
#define EMBD  1024
#define NHEAD 16
#define HDIM  64
#define BT    (BATCH*SEQ)        // 8192
#define C3    (3*EMBD)           // 3072

// ---------------------------------------------------------------------------
// Scratch (device globals — no allocation allowed)
// ---------------------------------------------------------------------------
__device__ __half g_qkvh[(size_t)BT * C3];
__device__ __half g_qkvl[(size_t)BT * C3];
__device__ __half g_xh[(size_t)BT * EMBD];
__device__ __half g_xl[(size_t)BT * EMBD];
__device__ __half g_wa[(size_t)EMBD * C3];      // weights: single fp16
__device__ __half g_wp[(size_t)EMBD * EMBD];    // weights: single fp16
__device__ __half g_yh[(size_t)BT * EMBD];
__device__ __half g_yl[(size_t)BT * EMBD];

// ---------------------------------------------------------------------------
// PTX helpers (sm_80+ portable: mma.sync / ldmatrix / cp.async)
// ---------------------------------------------------------------------------
__device__ __forceinline__ uint32_t smem_to_u32(const void* smem_ptr) {
    uint32_t addr;
    asm("{ .reg .u64 tmp; cvta.to.shared.u64 tmp, %1; cvt.u32.u64 %0, tmp; }"
        : "=r"(addr) : "l"(smem_ptr));
    return addr;
}

#define CP_ASYNC16(saddr, gptr) \
    asm volatile("cp.async.cg.shared.global [%0], [%1], 16;" \
        :: "r"(saddr), "l"(gptr) : "memory")
#define CP_ASYNC_COMMIT() asm volatile("cp.async.commit_group;" ::: "memory")
#define CP_ASYNC_WAIT0()  asm volatile("cp.async.wait_group 0;" ::: "memory")
#define CP_ASYNC_WAIT1()  asm volatile("cp.async.wait_group 1;" ::: "memory")

#define LDMATRIX_X4(r0,r1,r2,r3, addr) \
    asm volatile("ldmatrix.sync.aligned.m8n8.x4.shared.b16 {%0,%1,%2,%3}, [%4];" \
        : "=r"(r0), "=r"(r1), "=r"(r2), "=r"(r3) : "r"(addr))

#define LDMATRIX_X4_T(r0,r1,r2,r3, addr) \
    asm volatile("ldmatrix.sync.aligned.m8n8.x4.trans.shared.b16 {%0,%1,%2,%3}, [%4];" \
        : "=r"(r0), "=r"(r1), "=r"(r2), "=r"(r3) : "r"(addr))

// fp16 operands, fp32 accumulate
#define MMA_16816(d, a, b0v, b1v) \
    asm volatile( \
        "mma.sync.aligned.m16n8k16.row.col.f32.f16.f16.f32 " \
        "{%0,%1,%2,%3}, {%4,%5,%6,%7}, {%8,%9}, {%0,%1,%2,%3};" \
        : "+f"((d)[0]), "+f"((d)[1]), "+f"((d)[2]), "+f"((d)[3]) \
        : "r"((a)[0]), "r"((a)[1]), "r"((a)[2]), "r"((a)[3]), \
          "r"(b0v), "r"(b1v))

// split two fp32 into packed fp16x2 hi and lo
__device__ __forceinline__ void split2(float a, float b, uint32_t& h, uint32_t& l) {
    __half2 hh = __floats2half2_rn(a, b);
    float2 hf = __half22float2(hh);
    __half2 ll = __floats2half2_rn(a - hf.x, b - hf.y);
    h = *(uint32_t*)&hh;
    l = *(uint32_t*)&ll;
}

// ---------------------------------------------------------------------------
// Fused split: x -> fp16 hi/lo; W_attn, W_proj -> single fp16. One launch.
// ---------------------------------------------------------------------------
#define NX4  (BT * EMBD / 4)
#define NWA4 (EMBD * C3 / 4)
#define NWP4 (EMBD * EMBD / 4)
#define NSPLIT4 (NX4 + NWA4 + NWP4)

__global__ __launch_bounds__(256) void split_all_f16(
    const float* __restrict__ x, const float* __restrict__ wa,
    const float* __restrict__ wp,
    __half* __restrict__ xh, __half* __restrict__ xl,
    __half* __restrict__ wah, __half* __restrict__ wph)
{
    int i = blockIdx.x * 256 + threadIdx.x;
    if (i >= NSPLIT4) return;
    int j = i;
    if (j < NX4) {
        float4 v = ((const float4*)x)[j];
        uint32_t h0, l0, h1, l1;
        split2(v.x, v.y, h0, l0);
        split2(v.z, v.w, h1, l1);
        ((uint32_t*)xh)[2*j]     = h0;
        ((uint32_t*)xh)[2*j + 1] = h1;
        ((uint32_t*)xl)[2*j]     = l0;
        ((uint32_t*)xl)[2*j + 1] = l1;
        return;
    }
    j -= NX4;
    const float* src;
    __half* dst;
    if (j < NWA4) { src = wa; dst = wah; }
    else          { j -= NWA4; src = wp; dst = wph; }
    float4 v = ((const float4*)src)[j];
    __half2 p0 = __floats2half2_rn(v.x, v.y);
    __half2 p1 = __floats2half2_rn(v.z, v.w);
    ((uint32_t*)dst)[2*j]     = *(uint32_t*)&p0;
    ((uint32_t*)dst)[2*j + 1] = *(uint32_t*)&p1;
}

// ---------------------------------------------------------------------------
// fp16 asymmetric GEMM: C = (Ah + Al) @ B + bias.  2 MMA combos per tile
// (A split to 22 bits; B single fp16, rounding 2^-12 — dominant error term).
// 128x128 tile, 8 warps (64x32 each), cp.async double buffer.
// SPLIT_OUT=0: fp32 out (+bias). SPLIT_OUT=1: fp16 hi/lo out (+bias).
// ---------------------------------------------------------------------------
#define GOFF_AH 0u
#define GOFF_AL 10240u
#define GOFF_B  20480u
#define GBUF    29184u
#define GEMM_SMEM_BYTES (2u * GBUF)

template<int SPLIT_OUT>
__global__ __launch_bounds__(256) void gemm_mma_f16(
    const __half* __restrict__ Ah, const __half* __restrict__ Al,
    const __half* __restrict__ B,
    const float* __restrict__ bias, float* __restrict__ Cout,
    __half* __restrict__ Ch, __half* __restrict__ Cl,
    int M, int N, int K)
{
    extern __shared__ __align__(16) char smem[];
    const uint32_t sb = smem_to_u32(smem);
    const int tid  = threadIdx.x;
    const int warp = tid >> 5;
    const int lane = tid & 31;
    const int wm = warp & 1;
    const int wn = warp >> 1;
    const int row0 = blockIdx.y * 128;
    const int col0 = blockIdx.x * 128;

    const int ar = tid >> 2;
    const int ac = (tid & 3) * 8;
    const int bkr = tid >> 4;
    const int bnc = (tid & 15) * 8;

    const int nchunk = K >> 5;

    float acc[4][4][4];
    #pragma unroll
    for (int mt = 0; mt < 4; mt++)
        #pragma unroll
        for (int nt = 0; nt < 4; nt++)
            #pragma unroll
            for (int r = 0; r < 4; r++) acc[mt][nt][r] = 0.0f;

    {
        #pragma unroll
        for (int p = 0; p < 2; p++) {
            int r = ar + p * 64;
            CP_ASYNC16(sb + GOFF_AH + r*80 + ac*2, Ah + (size_t)(row0 + r) * K + ac);
            CP_ASYNC16(sb + GOFF_AL + r*80 + ac*2, Al + (size_t)(row0 + r) * K + ac);
            int kr = bkr + p * 16;
            CP_ASYNC16(sb + GOFF_B + kr*272 + bnc*2, B + (size_t)kr * N + col0 + bnc);
        }
        CP_ASYNC_COMMIT();
    }

    uint32_t buf = 0;
    for (int c = 0; c < nchunk; c++) {
        CP_ASYNC_WAIT0();
        __syncthreads();

        if (c + 1 < nchunk) {
            const uint32_t nb = sb + (buf ^ 1) * GBUF;
            const int kc0 = (c + 1) << 5;
            #pragma unroll
            for (int p = 0; p < 2; p++) {
                int r = ar + p * 64;
                CP_ASYNC16(nb + GOFF_AH + r*80 + ac*2, Ah + (size_t)(row0 + r) * K + kc0 + ac);
                CP_ASYNC16(nb + GOFF_AL + r*80 + ac*2, Al + (size_t)(row0 + r) * K + kc0 + ac);
                int kr = bkr + p * 16;
                CP_ASYNC16(nb + GOFF_B + kr*272 + bnc*2, B + (size_t)(kc0 + kr) * N + col0 + bnc);
            }
            CP_ASYNC_COMMIT();
        }

        const uint32_t cb = sb + buf * GBUF;
        #pragma unroll
        for (int s = 0; s < 2; s++) {
            uint32_t a_h[4][4], a_l[4][4];
            const int arow_base = wm * 64 + (lane & 15);
            const int acol = (s * 16 + (lane >> 4) * 8) * 2;
            #pragma unroll
            for (int mt = 0; mt < 4; mt++) {
                uint32_t off = (uint32_t)((arow_base + mt * 16) * 80 + acol);
                LDMATRIX_X4(a_h[mt][0], a_h[mt][1], a_h[mt][2], a_h[mt][3], cb + GOFF_AH + off);
                LDMATRIX_X4(a_l[mt][0], a_l[mt][1], a_l[mt][2], a_l[mt][3], cb + GOFF_AL + off);
            }
            uint32_t b_f[2][4];
            const int g = lane >> 3;
            const int krow = s * 16 + (g & 1) * 8 + (lane & 7);
            #pragma unroll
            for (int ntp = 0; ntp < 2; ntp++) {
                const int ncol = wn * 32 + ntp * 16 + (g >> 1) * 8;
                uint32_t off = (uint32_t)(krow * 272 + ncol * 2);
                LDMATRIX_X4_T(b_f[ntp][0], b_f[ntp][1], b_f[ntp][2], b_f[ntp][3], cb + GOFF_B + off);
            }
            // 2 combos: Ah*B, Al*B (combo-outer, distinct accumulators between reuses)
            #pragma unroll
            for (int combo = 0; combo < 2; combo++) {
                #pragma unroll
                for (int mt = 0; mt < 4; mt++) {
                    const uint32_t* av = combo ? a_l[mt] : a_h[mt];
                    #pragma unroll
                    for (int nt = 0; nt < 4; nt++) {
                        MMA_16816(acc[mt][nt], av,
                                  b_f[nt >> 1][(nt & 1) * 2],
                                  b_f[nt >> 1][(nt & 1) * 2 + 1]);
                    }
                }
            }
        }
        buf ^= 1;
    }

    const int er = (lane >> 2);
    const int ec = (lane & 3) * 2;
    #pragma unroll
    for (int mt = 0; mt < 4; mt++) {
        #pragma unroll
        for (int nt = 0; nt < 4; nt++) {
            const int r  = row0 + wm * 64 + mt * 16 + er;
            const int cc = col0 + wn * 32 + nt * 8 + ec;
            float2 bv = *(const float2*)(bias + cc);
            float o0x = acc[mt][nt][0] + bv.x;
            float o0y = acc[mt][nt][1] + bv.y;
            float o1x = acc[mt][nt][2] + bv.x;
            float o1y = acc[mt][nt][3] + bv.y;
            if (SPLIT_OUT) {
                uint32_t h0, l0, h1, l1;
                split2(o0x, o0y, h0, l0);
                split2(o1x, o1y, h1, l1);
                *(uint32_t*)(Ch + (size_t)r * N + cc)       = h0;
                *(uint32_t*)(Cl + (size_t)r * N + cc)       = l0;
                *(uint32_t*)(Ch + (size_t)(r + 8) * N + cc) = h1;
                *(uint32_t*)(Cl + (size_t)(r + 8) * N + cc) = l1;
            } else {
                *(float2*)(Cout + (size_t)r * N + cc)       = make_float2(o0x, o0y);
                *(float2*)(Cout + (size_t)(r + 8) * N + cc) = make_float2(o1x, o1y);
            }
        }
    }
}

// ---------------------------------------------------------------------------
// Flash attention (causal), fp16 3-combo (adds ~no error: residual ~2^-24).
// Structure identical to the best-measured R11 kernel (2-buffer KV).
// ---------------------------------------------------------------------------
#define BKV 64
#define AROW 144              // bytes per smem row
#define OKH 0u
#define OKL 9216u
#define OVH 18432u
#define OVL 27648u
#define ABUF 36864u
#define ATTN_SMEM_BYTES (2u * ABUF)

__global__ __launch_bounds__(256) void attn_mma(
    const __half* __restrict__ qkvh, const __half* __restrict__ qkvl,
    __half* __restrict__ Yh, __half* __restrict__ Yl)
{
    extern __shared__ __align__(16) char smem[];
    const uint32_t sb = smem_to_u32(smem);
    const int tid  = threadIdx.x;
    const int warp = tid >> 5;
    const int lane = tid & 31;

    const int qt = (int)(gridDim.x - 1 - blockIdx.x);   // heavy tiles first
    const int bh = blockIdx.y;
    const int b  = bh >> 4;
    const int h  = bh & 15;

    const size_t rowbase = (size_t)b * SEQ * C3 + h * HDIM;
    const __half* qh_g = qkvh + rowbase;
    const __half* ql_g = qkvl + rowbase;
    const __half* kh_g = qkvh + rowbase + EMBD;
    const __half* kl_g = qkvl + rowbase + EMBD;
    const __half* vh_g = qkvh + rowbase + 2 * EMBD;
    const __half* vl_g = qkvl + rowbase + 2 * EMBD;

    // ---- stage Q (128 rows x 64) hi/lo into smem, then to registers ----
    {
        #pragma unroll
        for (int it = 0; it < 4; it++) {
            int i = tid + it * 256;
            int row = i >> 3, ch = i & 7;
            const size_t go = (size_t)(qt * 128 + row) * C3 + ch * 8;
            CP_ASYNC16(sb + row * AROW + ch * 16,         qh_g + go);
            CP_ASYNC16(sb + 18432 + row * AROW + ch * 16, ql_g + go);
        }
        CP_ASYNC_COMMIT();
        CP_ASYNC_WAIT0();
        __syncthreads();
    }

    uint32_t aqh[4][4], aql[4][4];
    {
        const int arow = warp * 16 + (lane & 15);
        const int acby = (lane >> 4) * 16;
        #pragma unroll
        for (int kt4 = 0; kt4 < 4; kt4++) {
            uint32_t off = (uint32_t)(arow * AROW + kt4 * 32 + acby);
            LDMATRIX_X4(aqh[kt4][0], aqh[kt4][1], aqh[kt4][2], aqh[kt4][3], sb + off);
            LDMATRIX_X4(aql[kt4][0], aql[kt4][1], aql[kt4][2], aql[kt4][3], sb + 18432 + off);
        }
    }
    __syncthreads();   // done reading Q smem before K/V overwrite

    float m0 = -1e30f, m1 = -1e30f, l0 = 0.0f, l1 = 0.0f;
    float o[8][4];
    #pragma unroll
    for (int nt = 0; nt < 8; nt++)
        #pragma unroll
        for (int r = 0; r < 4; r++) o[nt][r] = 0.0f;

    const int nkv = 2 * qt + 2;

    // prefetch KV tiles 0 and 1
    #pragma unroll
    for (int pf = 0; pf < 2; pf++) {
        if (pf < nkv) {
            const uint32_t dst = sb + pf * ABUF;
            #pragma unroll
            for (int it = 0; it < 2; it++) {
                int i = tid + it * 256;
                int row = i >> 3, ch = i & 7;
                const size_t go = (size_t)(pf * BKV + row) * C3 + ch * 8;
                const uint32_t so = row * AROW + ch * 16;
                CP_ASYNC16(dst + OKH + so, kh_g + go);
                CP_ASYNC16(dst + OKL + so, kl_g + go);
                CP_ASYNC16(dst + OVH + so, vh_g + go);
                CP_ASYNC16(dst + OVL + so, vl_g + go);
            }
            CP_ASYNC_COMMIT();
        }
    }

    const float scale = 0.125f;  // 1/sqrt(64)

    for (int kt = 0; kt < nkv; kt++) {
        if (kt + 1 < nkv) { CP_ASYNC_WAIT1(); } else { CP_ASYNC_WAIT0(); }
        __syncthreads();

        const uint32_t cb = sb + (kt & 1) * ABUF;

        // ---- S = Qh*Kh^T + Qh*Kl^T + Ql*Kh^T  (m16 x n64, k=64) ----
        float s[8][4];
        #pragma unroll
        for (int nt = 0; nt < 8; nt++)
            #pragma unroll
            for (int r = 0; r < 4; r++) s[nt][r] = 0.0f;

        const int g = lane >> 3;
        #pragma unroll
        for (int kt4 = 0; kt4 < 4; kt4++) {
            uint32_t bkh[4][4], bkl[4][4];
            #pragma unroll
            for (int nt16 = 0; nt16 < 4; nt16++) {
                const int nrow = nt16 * 16 + (g & 1) * 8 + (lane & 7);
                const uint32_t off = (uint32_t)(nrow * AROW + kt4 * 32 + (g >> 1) * 16);
                LDMATRIX_X4(bkh[nt16][0], bkh[nt16][1], bkh[nt16][2], bkh[nt16][3], cb + OKH + off);
                LDMATRIX_X4(bkl[nt16][0], bkl[nt16][1], bkl[nt16][2], bkl[nt16][3], cb + OKL + off);
            }
            #pragma unroll
            for (int combo = 0; combo < 3; combo++) {
                const uint32_t* aq = (combo == 2) ? aql[kt4] : aqh[kt4];
                #pragma unroll
                for (int nt16 = 0; nt16 < 4; nt16++) {
                    #pragma unroll
                    for (int hv = 0; hv < 2; hv++) {
                        const int nt8 = nt16 * 2 + hv;
                        const uint32_t b0v = (combo == 1) ? bkl[nt16][hv]     : bkh[nt16][hv];
                        const uint32_t b1v = (combo == 1) ? bkl[nt16][2 + hv] : bkh[nt16][2 + hv];
                        MMA_16816(s[nt8], aq, b0v, b1v);
                    }
                }
            }
        }

        // ---- online softmax ----
        const bool need_mask = (kt >= 2 * qt);
        const int r0g = qt * 128 + warp * 16 + (lane >> 2);
        const int r1g = r0g + 8;
        float rmax0 = -1e30f, rmax1 = -1e30f;
        #pragma unroll
        for (int nt = 0; nt < 8; nt++) {
            #pragma unroll
            for (int j = 0; j < 2; j++) {
                const int kc = kt * BKV + nt * 8 + (lane & 3) * 2 + j;
                float v0 = s[nt][j] * scale;
                float v1 = s[nt][2 + j] * scale;
                if (need_mask) {
                    if (kc > r0g) v0 = -1e30f;
                    if (kc > r1g) v1 = -1e30f;
                }
                s[nt][j] = v0;     rmax0 = fmaxf(rmax0, v0);
                s[nt][2 + j] = v1; rmax1 = fmaxf(rmax1, v1);
            }
        }
        rmax0 = fmaxf(rmax0, __shfl_xor_sync(0xffffffffu, rmax0, 1));
        rmax0 = fmaxf(rmax0, __shfl_xor_sync(0xffffffffu, rmax0, 2));
        rmax1 = fmaxf(rmax1, __shfl_xor_sync(0xffffffffu, rmax1, 1));
        rmax1 = fmaxf(rmax1, __shfl_xor_sync(0xffffffffu, rmax1, 2));

        const float mn0 = fmaxf(m0, rmax0);
        const float mn1 = fmaxf(m1, rmax1);
        const float alpha0 = __expf(m0 - mn0);
        const float alpha1 = __expf(m1 - mn1);
        m0 = mn0; m1 = mn1;

        float ps0 = 0.0f, ps1 = 0.0f;
        #pragma unroll
        for (int nt = 0; nt < 8; nt++) {
            #pragma unroll
            for (int j = 0; j < 2; j++) {
                float p0 = __expf(s[nt][j] - mn0);
                float p1 = __expf(s[nt][2 + j] - mn1);
                s[nt][j] = p0;     ps0 += p0;
                s[nt][2 + j] = p1; ps1 += p1;
            }
        }
        ps0 += __shfl_xor_sync(0xffffffffu, ps0, 1);
        ps0 += __shfl_xor_sync(0xffffffffu, ps0, 2);
        ps1 += __shfl_xor_sync(0xffffffffu, ps1, 1);
        ps1 += __shfl_xor_sync(0xffffffffu, ps1, 2);
        l0 = l0 * alpha0 + ps0;
        l1 = l1 * alpha1 + ps1;

        #pragma unroll
        for (int nt = 0; nt < 8; nt++) {
            o[nt][0] *= alpha0; o[nt][1] *= alpha0;
            o[nt][2] *= alpha1; o[nt][3] *= alpha1;
        }

        // ---- pack P -> fp16 hi/lo A-fragments ----
        uint32_t aph[4][4], apl[4][4];
        #pragma unroll
        for (int pt = 0; pt < 4; pt++) {
            split2(s[2*pt][0],   s[2*pt][1],   aph[pt][0], apl[pt][0]);
            split2(s[2*pt][2],   s[2*pt][3],   aph[pt][1], apl[pt][1]);
            split2(s[2*pt+1][0], s[2*pt+1][1], aph[pt][2], apl[pt][2]);
            split2(s[2*pt+1][2], s[2*pt+1][3], aph[pt][3], apl[pt][3]);
        }

        // ---- O += P @ V ----
        #pragma unroll
        for (int pt = 0; pt < 4; pt++) {
            uint32_t bvh[4][4], bvl[4][4];
            #pragma unroll
            for (int nt16 = 0; nt16 < 4; nt16++) {
                const int krow = pt * 16 + (g & 1) * 8 + (lane & 7);
                const uint32_t off = (uint32_t)(krow * AROW + nt16 * 32 + (g >> 1) * 16);
                LDMATRIX_X4_T(bvh[nt16][0], bvh[nt16][1], bvh[nt16][2], bvh[nt16][3], cb + OVH + off);
                LDMATRIX_X4_T(bvl[nt16][0], bvl[nt16][1], bvl[nt16][2], bvl[nt16][3], cb + OVL + off);
            }
            #pragma unroll
            for (int combo = 0; combo < 3; combo++) {
                const uint32_t* ap = (combo == 2) ? apl[pt] : aph[pt];
                #pragma unroll
                for (int nt16 = 0; nt16 < 4; nt16++) {
                    #pragma unroll
                    for (int hv = 0; hv < 2; hv++) {
                        const int nt8 = nt16 * 2 + hv;
                        const uint32_t b0v = (combo == 1) ? bvl[nt16][hv * 2]     : bvh[nt16][hv * 2];
                        const uint32_t b1v = (combo == 1) ? bvl[nt16][hv * 2 + 1] : bvh[nt16][hv * 2 + 1];
                        MMA_16816(o[nt8], ap, b0v, b1v);
                    }
                }
            }
        }

        __syncthreads();   // all warps done with this buffer

        if (kt + 2 < nkv) {
            const uint32_t dst = sb + (kt & 1) * ABUF;
            #pragma unroll
            for (int it = 0; it < 2; it++) {
                int i = tid + it * 256;
                int row = i >> 3, ch = i & 7;
                const size_t go = (size_t)((kt + 2) * BKV + row) * C3 + ch * 8;
                const uint32_t so = row * AROW + ch * 16;
                CP_ASYNC16(dst + OKH + so, kh_g + go);
                CP_ASYNC16(dst + OKL + so, kl_g + go);
                CP_ASYNC16(dst + OVH + so, vh_g + go);
                CP_ASYNC16(dst + OVL + so, vl_g + go);
            }
            CP_ASYNC_COMMIT();
        }
    }

    // ---- epilogue: normalize, split to fp16 hi/lo, store ----
    const float inv0 = 1.0f / l0;
    const float inv1 = 1.0f / l1;
    const int tr0 = qt * 128 + warp * 16 + (lane >> 2);
    const size_t ybase = (size_t)b * SEQ * EMBD + h * HDIM;
    #pragma unroll
    for (int nt = 0; nt < 8; nt++) {
        const int col = nt * 8 + (lane & 3) * 2;
        uint32_t h0, lo0, h1, lo1;
        split2(o[nt][0] * inv0, o[nt][1] * inv0, h0, lo0);
        split2(o[nt][2] * inv1, o[nt][3] * inv1, h1, lo1);
        *(uint32_t*)(Yh + ybase + (size_t)tr0 * EMBD + col)       = h0;
        *(uint32_t*)(Yl + ybase + (size_t)tr0 * EMBD + col)       = lo0;
        *(uint32_t*)(Yh + ybase + (size_t)(tr0 + 8) * EMBD + col) = h1;
        *(uint32_t*)(Yl + ybase + (size_t)(tr0 + 8) * EMBD + col) = lo1;
    }
}

// ---------------------------------------------------------------------------
extern "C" void kernel_launch(void* const* d_in, const int* in_sizes, int n_in,
                              void* d_out, int out_size)
{
    const float* x      = (const float*)d_in[0];
    const float* W_attn = (const float*)d_in[1];
    const float* b_attn = (const float*)d_in[2];
    const float* W_proj = (const float*)d_in[3];
    const float* b_proj = (const float*)d_in[4];
    float* out = (float*)d_out;

    __half *qkvh, *qkvl, *xh, *xl, *wa, *wp, *yh, *yl;
    cudaGetSymbolAddress((void**)&qkvh, g_qkvh);
    cudaGetSymbolAddress((void**)&qkvl, g_qkvl);
    cudaGetSymbolAddress((void**)&xh,  g_xh);
    cudaGetSymbolAddress((void**)&xl,  g_xl);
    cudaGetSymbolAddress((void**)&wa,  g_wa);
    cudaGetSymbolAddress((void**)&wp,  g_wp);
    cudaGetSymbolAddress((void**)&yh,  g_yh);
    cudaGetSymbolAddress((void**)&yl,  g_yl);

    cudaFuncSetAttribute(gemm_mma_f16<0>,
                         cudaFuncAttributeMaxDynamicSharedMemorySize, GEMM_SMEM_BYTES);
    cudaFuncSetAttribute(gemm_mma_f16<1>,
                         cudaFuncAttributeMaxDynamicSharedMemorySize, GEMM_SMEM_BYTES);
    cudaFuncSetAttribute(attn_mma,
                         cudaFuncAttributeMaxDynamicSharedMemorySize, ATTN_SMEM_BYTES);

    // 0) fused split: x -> hi/lo, weights -> single fp16
    {
        split_all_f16<<<(NSPLIT4 + 255) / 256, 256>>>(
            x, W_attn, W_proj, xh, xl, wa, wp);
    }
    // 1) QKV GEMM (2 MMA combos) -> fp16 hi/lo qkv
    {
        dim3 grid(C3 / 128, BT / 128);
        gemm_mma_f16<1><<<grid, 256, GEMM_SMEM_BYTES>>>(
            xh, xl, wa, b_attn, nullptr, qkvh, qkvl, BT, C3, EMBD);
    }
    // 2) causal flash attention (fp16 3-combo) -> fp16 hi/lo y
    {
        dim3 grid(SEQ / 128, BATCH * NHEAD);
        attn_mma<<<grid, 256, ATTN_SMEM_BYTES>>>(qkvh, qkvl, yh, yl);
    }
    // 3) proj GEMM (2 MMA combos) -> fp32 out
    {
        dim3 grid(EMBD / 128, BT / 128);
        gemm_mma_f16<0><<<grid, 256, GEMM_SMEM_BYTES>>>(
            yh, yl, wp, b_proj, out, nullptr, nullptr, BT, EMBD, EMBD);
    }
}

// round 17
// speedup vs baseline: 1.3084x; 1.1214x over previous
#include <cuda_runtime.h>
#include <cuda_fp16.h>
#include <cstdint>

// ---------------------------------------------------------------------------
// Problem constants
// ---------------------------------------------------------------------------
#define BATCH 4
#define SEQ   2048
#define EMBD  1024
#define NHEAD 16
#define HDIM  64
#define BT    (BATCH*SEQ)        // 8192
#define C3    (3*EMBD)           // 3072

// ---------------------------------------------------------------------------
// Scratch (device globals — no allocation allowed)
// ---------------------------------------------------------------------------
__device__ __half g_qkvh[(size_t)BT * C3];
__device__ __half g_qkvl[(size_t)BT * C3];
__device__ __half g_xh[(size_t)BT * EMBD];
__device__ __half g_xl[(size_t)BT * EMBD];
__device__ __half g_wa[(size_t)EMBD * C3];      // weights: single fp16
__device__ __half g_wp[(size_t)EMBD * EMBD];    // weights: single fp16
__device__ __half g_yh[(size_t)BT * EMBD];
__device__ __half g_yl[(size_t)BT * EMBD];

// ---------------------------------------------------------------------------
// PTX helpers (sm_80+ portable: mma.sync / ldmatrix / cp.async)
// ---------------------------------------------------------------------------
__device__ __forceinline__ uint32_t smem_to_u32(const void* smem_ptr) {
    uint32_t addr;
    asm("{ .reg .u64 tmp; cvta.to.shared.u64 tmp, %1; cvt.u32.u64 %0, tmp; }"
        : "=r"(addr) : "l"(smem_ptr));
    return addr;
}

#define CP_ASYNC16(saddr, gptr) \
    asm volatile("cp.async.cg.shared.global [%0], [%1], 16;" \
        :: "r"(saddr), "l"(gptr) : "memory")
#define CP_ASYNC_COMMIT() asm volatile("cp.async.commit_group;" ::: "memory")
#define CP_ASYNC_WAIT0()  asm volatile("cp.async.wait_group 0;" ::: "memory")
#define CP_ASYNC_WAIT1()  asm volatile("cp.async.wait_group 1;" ::: "memory")

#define LDMATRIX_X4(r0,r1,r2,r3, addr) \
    asm volatile("ldmatrix.sync.aligned.m8n8.x4.shared.b16 {%0,%1,%2,%3}, [%4];" \
        : "=r"(r0), "=r"(r1), "=r"(r2), "=r"(r3) : "r"(addr))

#define LDMATRIX_X4_T(r0,r1,r2,r3, addr) \
    asm volatile("ldmatrix.sync.aligned.m8n8.x4.trans.shared.b16 {%0,%1,%2,%3}, [%4];" \
        : "=r"(r0), "=r"(r1), "=r"(r2), "=r"(r3) : "r"(addr))

// fp16 operands, fp32 accumulate
#define MMA_16816(d, a, b0v, b1v) \
    asm volatile( \
        "mma.sync.aligned.m16n8k16.row.col.f32.f16.f16.f32 " \
        "{%0,%1,%2,%3}, {%4,%5,%6,%7}, {%8,%9}, {%0,%1,%2,%3};" \
        : "+f"((d)[0]), "+f"((d)[1]), "+f"((d)[2]), "+f"((d)[3]) \
        : "r"((a)[0]), "r"((a)[1]), "r"((a)[2]), "r"((a)[3]), \
          "r"(b0v), "r"(b1v))

// split two fp32 into packed fp16x2 hi and lo
__device__ __forceinline__ void split2(float a, float b, uint32_t& h, uint32_t& l) {
    __half2 hh = __floats2half2_rn(a, b);
    float2 hf = __half22float2(hh);
    __half2 ll = __floats2half2_rn(a - hf.x, b - hf.y);
    h = *(uint32_t*)&hh;
    l = *(uint32_t*)&ll;
}

// ---------------------------------------------------------------------------
// Fused split: x -> fp16 hi/lo; W_attn, W_proj -> single fp16. One launch.
// ---------------------------------------------------------------------------
#define NX4  (BT * EMBD / 4)
#define NWA4 (EMBD * C3 / 4)
#define NWP4 (EMBD * EMBD / 4)
#define NSPLIT4 (NX4 + NWA4 + NWP4)

__global__ __launch_bounds__(256) void split_all_f16(
    const float* __restrict__ x, const float* __restrict__ wa,
    const float* __restrict__ wp,
    __half* __restrict__ xh, __half* __restrict__ xl,
    __half* __restrict__ wah, __half* __restrict__ wph)
{
    int i = blockIdx.x * 256 + threadIdx.x;
    if (i >= NSPLIT4) return;
    int j = i;
    if (j < NX4) {
        float4 v = ((const float4*)x)[j];
        uint32_t h0, l0, h1, l1;
        split2(v.x, v.y, h0, l0);
        split2(v.z, v.w, h1, l1);
        ((uint32_t*)xh)[2*j]     = h0;
        ((uint32_t*)xh)[2*j + 1] = h1;
        ((uint32_t*)xl)[2*j]     = l0;
        ((uint32_t*)xl)[2*j + 1] = l1;
        return;
    }
    j -= NX4;
    const float* src;
    __half* dst;
    if (j < NWA4) { src = wa; dst = wah; }
    else          { j -= NWA4; src = wp; dst = wph; }
    float4 v = ((const float4*)src)[j];
    __half2 p0 = __floats2half2_rn(v.x, v.y);
    __half2 p1 = __floats2half2_rn(v.z, v.w);
    ((uint32_t*)dst)[2*j]     = *(uint32_t*)&p0;
    ((uint32_t*)dst)[2*j + 1] = *(uint32_t*)&p1;
}

// ---------------------------------------------------------------------------
// fp16 asymmetric GEMM: C = (Ah + Al) @ B + bias — unchanged from R14 passing.
// ---------------------------------------------------------------------------
#define GOFF_AH 0u
#define GOFF_AL 10240u
#define GOFF_B  20480u
#define GBUF    29184u
#define GEMM_SMEM_BYTES (2u * GBUF)

template<int SPLIT_OUT>
__global__ __launch_bounds__(256) void gemm_mma_f16(
    const __half* __restrict__ Ah, const __half* __restrict__ Al,
    const __half* __restrict__ B,
    const float* __restrict__ bias, float* __restrict__ Cout,
    __half* __restrict__ Ch, __half* __restrict__ Cl,
    int M, int N, int K)
{
    extern __shared__ __align__(16) char smem[];
    const uint32_t sb = smem_to_u32(smem);
    const int tid  = threadIdx.x;
    const int warp = tid >> 5;
    const int lane = tid & 31;
    const int wm = warp & 1;
    const int wn = warp >> 1;
    const int row0 = blockIdx.y * 128;
    const int col0 = blockIdx.x * 128;

    const int ar = tid >> 2;
    const int ac = (tid & 3) * 8;
    const int bkr = tid >> 4;
    const int bnc = (tid & 15) * 8;

    const int nchunk = K >> 5;

    float acc[4][4][4];
    #pragma unroll
    for (int mt = 0; mt < 4; mt++)
        #pragma unroll
        for (int nt = 0; nt < 4; nt++)
            #pragma unroll
            for (int r = 0; r < 4; r++) acc[mt][nt][r] = 0.0f;

    {
        #pragma unroll
        for (int p = 0; p < 2; p++) {
            int r = ar + p * 64;
            CP_ASYNC16(sb + GOFF_AH + r*80 + ac*2, Ah + (size_t)(row0 + r) * K + ac);
            CP_ASYNC16(sb + GOFF_AL + r*80 + ac*2, Al + (size_t)(row0 + r) * K + ac);
            int kr = bkr + p * 16;
            CP_ASYNC16(sb + GOFF_B + kr*272 + bnc*2, B + (size_t)kr * N + col0 + bnc);
        }
        CP_ASYNC_COMMIT();
    }

    uint32_t buf = 0;
    for (int c = 0; c < nchunk; c++) {
        CP_ASYNC_WAIT0();
        __syncthreads();

        if (c + 1 < nchunk) {
            const uint32_t nb = sb + (buf ^ 1) * GBUF;
            const int kc0 = (c + 1) << 5;
            #pragma unroll
            for (int p = 0; p < 2; p++) {
                int r = ar + p * 64;
                CP_ASYNC16(nb + GOFF_AH + r*80 + ac*2, Ah + (size_t)(row0 + r) * K + kc0 + ac);
                CP_ASYNC16(nb + GOFF_AL + r*80 + ac*2, Al + (size_t)(row0 + r) * K + kc0 + ac);
                int kr = bkr + p * 16;
                CP_ASYNC16(nb + GOFF_B + kr*272 + bnc*2, B + (size_t)(kc0 + kr) * N + col0 + bnc);
            }
            CP_ASYNC_COMMIT();
        }

        const uint32_t cb = sb + buf * GBUF;
        #pragma unroll
        for (int s = 0; s < 2; s++) {
            uint32_t a_h[4][4], a_l[4][4];
            const int arow_base = wm * 64 + (lane & 15);
            const int acol = (s * 16 + (lane >> 4) * 8) * 2;
            #pragma unroll
            for (int mt = 0; mt < 4; mt++) {
                uint32_t off = (uint32_t)((arow_base + mt * 16) * 80 + acol);
                LDMATRIX_X4(a_h[mt][0], a_h[mt][1], a_h[mt][2], a_h[mt][3], cb + GOFF_AH + off);
                LDMATRIX_X4(a_l[mt][0], a_l[mt][1], a_l[mt][2], a_l[mt][3], cb + GOFF_AL + off);
            }
            uint32_t b_f[2][4];
            const int g = lane >> 3;
            const int krow = s * 16 + (g & 1) * 8 + (lane & 7);
            #pragma unroll
            for (int ntp = 0; ntp < 2; ntp++) {
                const int ncol = wn * 32 + ntp * 16 + (g >> 1) * 8;
                uint32_t off = (uint32_t)(krow * 272 + ncol * 2);
                LDMATRIX_X4_T(b_f[ntp][0], b_f[ntp][1], b_f[ntp][2], b_f[ntp][3], cb + GOFF_B + off);
            }
            #pragma unroll
            for (int combo = 0; combo < 2; combo++) {
                #pragma unroll
                for (int mt = 0; mt < 4; mt++) {
                    const uint32_t* av = combo ? a_l[mt] : a_h[mt];
                    #pragma unroll
                    for (int nt = 0; nt < 4; nt++) {
                        MMA_16816(acc[mt][nt], av,
                                  b_f[nt >> 1][(nt & 1) * 2],
                                  b_f[nt >> 1][(nt & 1) * 2 + 1]);
                    }
                }
            }
        }
        buf ^= 1;
    }

    const int er = (lane >> 2);
    const int ec = (lane & 3) * 2;
    #pragma unroll
    for (int mt = 0; mt < 4; mt++) {
        #pragma unroll
        for (int nt = 0; nt < 4; nt++) {
            const int r  = row0 + wm * 64 + mt * 16 + er;
            const int cc = col0 + wn * 32 + nt * 8 + ec;
            float2 bv = *(const float2*)(bias + cc);
            float o0x = acc[mt][nt][0] + bv.x;
            float o0y = acc[mt][nt][1] + bv.y;
            float o1x = acc[mt][nt][2] + bv.x;
            float o1y = acc[mt][nt][3] + bv.y;
            if (SPLIT_OUT) {
                uint32_t h0, l0, h1, l1;
                split2(o0x, o0y, h0, l0);
                split2(o1x, o1y, h1, l1);
                *(uint32_t*)(Ch + (size_t)r * N + cc)       = h0;
                *(uint32_t*)(Cl + (size_t)r * N + cc)       = l0;
                *(uint32_t*)(Ch + (size_t)(r + 8) * N + cc) = h1;
                *(uint32_t*)(Cl + (size_t)(r + 8) * N + cc) = l1;
            } else {
                *(float2*)(Cout + (size_t)r * N + cc)       = make_float2(o0x, o0y);
                *(float2*)(Cout + (size_t)(r + 8) * N + cc) = make_float2(o1x, o1y);
            }
        }
    }
}

// ---------------------------------------------------------------------------
// Flash attention (causal), asymmetric fp16:
//   Q hi/lo (registers), K single fp16, V single fp16, P hi/lo.
//   S = Qh·K + Ql·K   (2 combos, error = K rounding ~2^-12)
//   O = Ph·V + Pl·V   (2 combos, error = V rounding ~2^-12)
// MMAs/tile 192 -> 128; KV smem + cp.async traffic halved.
// ---------------------------------------------------------------------------
#define BKV 64
#define AROW 144              // bytes per smem row
#define OK  0u
#define OV  9216u
#define ABUF 18432u
#define ATTN_SMEM_BYTES 36864u   // max(2 KV buffers, Q hi/lo staging)

__global__ __launch_bounds__(256) void attn_mma(
    const __half* __restrict__ qkvh, const __half* __restrict__ qkvl,
    __half* __restrict__ Yh, __half* __restrict__ Yl)
{
    extern __shared__ __align__(16) char smem[];
    const uint32_t sb = smem_to_u32(smem);
    const int tid  = threadIdx.x;
    const int warp = tid >> 5;
    const int lane = tid & 31;

    const int qt = (int)(gridDim.x - 1 - blockIdx.x);   // heavy tiles first
    const int bh = blockIdx.y;
    const int b  = bh >> 4;
    const int h  = bh & 15;

    const size_t rowbase = (size_t)b * SEQ * C3 + h * HDIM;
    const __half* qh_g = qkvh + rowbase;
    const __half* ql_g = qkvl + rowbase;
    const __half* k_g  = qkvh + rowbase + EMBD;        // K: hi plane only
    const __half* v_g  = qkvh + rowbase + 2 * EMBD;    // V: hi plane only

    // ---- stage Q (128 rows x 64) hi/lo into smem, then to registers ----
    {
        #pragma unroll
        for (int it = 0; it < 4; it++) {
            int i = tid + it * 256;
            int row = i >> 3, ch = i & 7;
            const size_t go = (size_t)(qt * 128 + row) * C3 + ch * 8;
            CP_ASYNC16(sb + row * AROW + ch * 16,         qh_g + go);
            CP_ASYNC16(sb + 18432 + row * AROW + ch * 16, ql_g + go);
        }
        CP_ASYNC_COMMIT();
        CP_ASYNC_WAIT0();
        __syncthreads();
    }

    uint32_t aqh[4][4], aql[4][4];
    {
        const int arow = warp * 16 + (lane & 15);
        const int acby = (lane >> 4) * 16;
        #pragma unroll
        for (int kt4 = 0; kt4 < 4; kt4++) {
            uint32_t off = (uint32_t)(arow * AROW + kt4 * 32 + acby);
            LDMATRIX_X4(aqh[kt4][0], aqh[kt4][1], aqh[kt4][2], aqh[kt4][3], sb + off);
            LDMATRIX_X4(aql[kt4][0], aql[kt4][1], aql[kt4][2], aql[kt4][3], sb + 18432 + off);
        }
    }
    __syncthreads();   // done reading Q smem before K/V overwrite

    float m0 = -1e30f, m1 = -1e30f, l0 = 0.0f, l1 = 0.0f;
    float o[8][4];
    #pragma unroll
    for (int nt = 0; nt < 8; nt++)
        #pragma unroll
        for (int r = 0; r < 4; r++) o[nt][r] = 0.0f;

    const int nkv = 2 * qt + 2;

    // prefetch KV tiles 0 and 1 (single-plane K and V)
    #pragma unroll
    for (int pf = 0; pf < 2; pf++) {
        if (pf < nkv) {
            const uint32_t dst = sb + pf * ABUF;
            #pragma unroll
            for (int it = 0; it < 2; it++) {
                int i = tid + it * 256;
                int row = i >> 3, ch = i & 7;
                const size_t go = (size_t)(pf * BKV + row) * C3 + ch * 8;
                const uint32_t so = row * AROW + ch * 16;
                CP_ASYNC16(dst + OK + so, k_g + go);
                CP_ASYNC16(dst + OV + so, v_g + go);
            }
            CP_ASYNC_COMMIT();
        }
    }

    const float scale = 0.125f;  // 1/sqrt(64)

    for (int kt = 0; kt < nkv; kt++) {
        if (kt + 1 < nkv) { CP_ASYNC_WAIT1(); } else { CP_ASYNC_WAIT0(); }
        __syncthreads();

        const uint32_t cb = sb + (kt & 1) * ABUF;

        // ---- S = Qh·K + Ql·K  (m16 x n64, k=64) ----
        float s[8][4];
        #pragma unroll
        for (int nt = 0; nt < 8; nt++)
            #pragma unroll
            for (int r = 0; r < 4; r++) s[nt][r] = 0.0f;

        const int g = lane >> 3;
        #pragma unroll
        for (int kt4 = 0; kt4 < 4; kt4++) {
            uint32_t bk[4][4];
            #pragma unroll
            for (int nt16 = 0; nt16 < 4; nt16++) {
                const int nrow = nt16 * 16 + (g & 1) * 8 + (lane & 7);
                const uint32_t off = (uint32_t)(nrow * AROW + kt4 * 32 + (g >> 1) * 16);
                LDMATRIX_X4(bk[nt16][0], bk[nt16][1], bk[nt16][2], bk[nt16][3], cb + OK + off);
            }
            #pragma unroll
            for (int combo = 0; combo < 2; combo++) {
                const uint32_t* aq = combo ? aql[kt4] : aqh[kt4];
                #pragma unroll
                for (int nt16 = 0; nt16 < 4; nt16++) {
                    #pragma unroll
                    for (int hv = 0; hv < 2; hv++) {
                        const int nt8 = nt16 * 2 + hv;
                        MMA_16816(s[nt8], aq, bk[nt16][hv], bk[nt16][2 + hv]);
                    }
                }
            }
        }

        // ---- online softmax ----
        const bool need_mask = (kt >= 2 * qt);
        const int r0g = qt * 128 + warp * 16 + (lane >> 2);
        const int r1g = r0g + 8;
        float rmax0 = -1e30f, rmax1 = -1e30f;
        #pragma unroll
        for (int nt = 0; nt < 8; nt++) {
            #pragma unroll
            for (int j = 0; j < 2; j++) {
                const int kc = kt * BKV + nt * 8 + (lane & 3) * 2 + j;
                float v0 = s[nt][j] * scale;
                float v1 = s[nt][2 + j] * scale;
                if (need_mask) {
                    if (kc > r0g) v0 = -1e30f;
                    if (kc > r1g) v1 = -1e30f;
                }
                s[nt][j] = v0;     rmax0 = fmaxf(rmax0, v0);
                s[nt][2 + j] = v1; rmax1 = fmaxf(rmax1, v1);
            }
        }
        rmax0 = fmaxf(rmax0, __shfl_xor_sync(0xffffffffu, rmax0, 1));
        rmax0 = fmaxf(rmax0, __shfl_xor_sync(0xffffffffu, rmax0, 2));
        rmax1 = fmaxf(rmax1, __shfl_xor_sync(0xffffffffu, rmax1, 1));
        rmax1 = fmaxf(rmax1, __shfl_xor_sync(0xffffffffu, rmax1, 2));

        const float mn0 = fmaxf(m0, rmax0);
        const float mn1 = fmaxf(m1, rmax1);
        const float alpha0 = __expf(m0 - mn0);
        const float alpha1 = __expf(m1 - mn1);
        m0 = mn0; m1 = mn1;

        float ps0 = 0.0f, ps1 = 0.0f;
        #pragma unroll
        for (int nt = 0; nt < 8; nt++) {
            #pragma unroll
            for (int j = 0; j < 2; j++) {
                float p0 = __expf(s[nt][j] - mn0);
                float p1 = __expf(s[nt][2 + j] - mn1);
                s[nt][j] = p0;     ps0 += p0;
                s[nt][2 + j] = p1; ps1 += p1;
            }
        }
        ps0 += __shfl_xor_sync(0xffffffffu, ps0, 1);
        ps0 += __shfl_xor_sync(0xffffffffu, ps0, 2);
        ps1 += __shfl_xor_sync(0xffffffffu, ps1, 1);
        ps1 += __shfl_xor_sync(0xffffffffu, ps1, 2);
        l0 = l0 * alpha0 + ps0;
        l1 = l1 * alpha1 + ps1;

        #pragma unroll
        for (int nt = 0; nt < 8; nt++) {
            o[nt][0] *= alpha0; o[nt][1] *= alpha0;
            o[nt][2] *= alpha1; o[nt][3] *= alpha1;
        }

        // ---- pack P -> fp16 hi/lo A-fragments ----
        uint32_t aph[4][4], apl[4][4];
        #pragma unroll
        for (int pt = 0; pt < 4; pt++) {
            split2(s[2*pt][0],   s[2*pt][1],   aph[pt][0], apl[pt][0]);
            split2(s[2*pt][2],   s[2*pt][3],   aph[pt][1], apl[pt][1]);
            split2(s[2*pt+1][0], s[2*pt+1][1], aph[pt][2], apl[pt][2]);
            split2(s[2*pt+1][2], s[2*pt+1][3], aph[pt][3], apl[pt][3]);
        }

        // ---- O += Ph·V + Pl·V ----
        #pragma unroll
        for (int pt = 0; pt < 4; pt++) {
            uint32_t bv[4][4];
            #pragma unroll
            for (int nt16 = 0; nt16 < 4; nt16++) {
                const int krow = pt * 16 + (g & 1) * 8 + (lane & 7);
                const uint32_t off = (uint32_t)(krow * AROW + nt16 * 32 + (g >> 1) * 16);
                LDMATRIX_X4_T(bv[nt16][0], bv[nt16][1], bv[nt16][2], bv[nt16][3], cb + OV + off);
            }
            #pragma unroll
            for (int combo = 0; combo < 2; combo++) {
                const uint32_t* ap = combo ? apl[pt] : aph[pt];
                #pragma unroll
                for (int nt16 = 0; nt16 < 4; nt16++) {
                    #pragma unroll
                    for (int hv = 0; hv < 2; hv++) {
                        const int nt8 = nt16 * 2 + hv;
                        MMA_16816(o[nt8], ap, bv[nt16][hv * 2], bv[nt16][hv * 2 + 1]);
                    }
                }
            }
        }

        __syncthreads();   // all warps done with this buffer

        if (kt + 2 < nkv) {
            const uint32_t dst = sb + (kt & 1) * ABUF;
            #pragma unroll
            for (int it = 0; it < 2; it++) {
                int i = tid + it * 256;
                int row = i >> 3, ch = i & 7;
                const size_t go = (size_t)((kt + 2) * BKV + row) * C3 + ch * 8;
                const uint32_t so = row * AROW + ch * 16;
                CP_ASYNC16(dst + OK + so, k_g + go);
                CP_ASYNC16(dst + OV + so, v_g + go);
            }
            CP_ASYNC_COMMIT();
        }
    }

    // ---- epilogue: normalize, split to fp16 hi/lo, store ----
    const float inv0 = 1.0f / l0;
    const float inv1 = 1.0f / l1;
    const int tr0 = qt * 128 + warp * 16 + (lane >> 2);
    const size_t ybase = (size_t)b * SEQ * EMBD + h * HDIM;
    #pragma unroll
    for (int nt = 0; nt < 8; nt++) {
        const int col = nt * 8 + (lane & 3) * 2;
        uint32_t h0, lo0, h1, lo1;
        split2(o[nt][0] * inv0, o[nt][1] * inv0, h0, lo0);
        split2(o[nt][2] * inv1, o[nt][3] * inv1, h1, lo1);
        *(uint32_t*)(Yh + ybase + (size_t)tr0 * EMBD + col)       = h0;
        *(uint32_t*)(Yl + ybase + (size_t)tr0 * EMBD + col)       = lo0;
        *(uint32_t*)(Yh + ybase + (size_t)(tr0 + 8) * EMBD + col) = h1;
        *(uint32_t*)(Yl + ybase + (size_t)(tr0 + 8) * EMBD + col) = lo1;
    }
}

// ---------------------------------------------------------------------------
extern "C" void kernel_launch(void* const* d_in, const int* in_sizes, int n_in,
                              void* d_out, int out_size)
{
    const float* x      = (const float*)d_in[0];
    const float* W_attn = (const float*)d_in[1];
    const float* b_attn = (const float*)d_in[2];
    const float* W_proj = (const float*)d_in[3];
    const float* b_proj = (const float*)d_in[4];
    float* out = (float*)d_out;

    __half *qkvh, *qkvl, *xh, *xl, *wa, *wp, *yh, *yl;
    cudaGetSymbolAddress((void**)&qkvh, g_qkvh);
    cudaGetSymbolAddress((void**)&qkvl, g_qkvl);
    cudaGetSymbolAddress((void**)&xh,  g_xh);
    cudaGetSymbolAddress((void**)&xl,  g_xl);
    cudaGetSymbolAddress((void**)&wa,  g_wa);
    cudaGetSymbolAddress((void**)&wp,  g_wp);
    cudaGetSymbolAddress((void**)&yh,  g_yh);
    cudaGetSymbolAddress((void**)&yl,  g_yl);

    cudaFuncSetAttribute(gemm_mma_f16<0>,
                         cudaFuncAttributeMaxDynamicSharedMemorySize, GEMM_SMEM_BYTES);
    cudaFuncSetAttribute(gemm_mma_f16<1>,
                         cudaFuncAttributeMaxDynamicSharedMemorySize, GEMM_SMEM_BYTES);
    cudaFuncSetAttribute(attn_mma,
                         cudaFuncAttributeMaxDynamicSharedMemorySize, ATTN_SMEM_BYTES);

    // 0) fused split: x -> hi/lo, weights -> single fp16
    {
        split_all_f16<<<(NSPLIT4 + 255) / 256, 256>>>(
            x, W_attn, W_proj, xh, xl, wa, wp);
    }
    // 1) QKV GEMM (2 MMA combos) -> fp16 hi/lo qkv
    {
        dim3 grid(C3 / 128, BT / 128);
        gemm_mma_f16<1><<<grid, 256, GEMM_SMEM_BYTES>>>(
            xh, xl, wa, b_attn, nullptr, qkvh, qkvl, BT, C3, EMBD);
    }
    // 2) causal flash attention (asymmetric fp16: K,V single) -> fp16 hi/lo y
    {
        dim3 grid(SEQ / 128, BATCH * NHEAD);
        attn_mma<<<grid, 256, ATTN_SMEM_BYTES>>>(qkvh, qkvl, yh, yl);
    }
    // 3) proj GEMM (2 MMA combos) -> fp32 out
    {
        dim3 grid(EMBD / 128, BT / 128);
        gemm_mma_f16<0><<<grid, 256, GEMM_SMEM_BYTES>>>(
            yh, yl, wp, b_proj, out, nullptr, nullptr, BT, EMBD, EMBD);
    }
}